// round 14
// baseline (speedup 1.0000x reference)
#include <cuda_runtime.h>
#include <cuda_fp16.h>
#include <math.h>
#include <stdint.h>

// ---------------- problem constants ----------------
#define NN       8192
#define D_IN     120
#define NODE_D   128
#define HID      64
#define NPW      17536     // num path weights
#define NB       336       // num bias
#define OUTD     60        // out is [N, 60, 60]
#define NCHUNK   4
#define CHN      (NN / NCHUNK)   // 2048 nodes per chunk

// scratch (device globals: allocation-free rule)
__device__ float  g_H[NN * HID];
__device__ float  g_G[NN * HID];
__device__ float  g_bias[NN * NB];
__device__ __half g_weight_h[(size_t)NN * NPW];   // PERMUTED layout [path][w_hi][uv][w_lo=8]
__device__ float  g_w3j[363];
__device__ float  g_w2wt[HID * NPW];              // w2w with permuted columns
__device__ float  g_b2wt[NPW];                    // b2w permuted

__device__ __forceinline__ uint32_t smem_u32(const void* p) {
    uint32_t a;
    asm("{ .reg .u64 t; cvta.to.shared.u64 t, %1; cvt.u32.u64 %0, t; }" : "=r"(a) : "l"(p));
    return a;
}

// ---------------- path tables ----------------
__constant__ int pOFF[12] = {0,8192,10240,10752,12800,14848,15360,15872,16384,16896,17408,17536};
__constant__ int pUV[11]  = {256,64,16,128,128,32,32,64,64,64,16};

// ---------------- Wigner 3j init (parallel, fp64, mirrors reference) ----------------
__device__ double dfac(int n) { double r = 1.0; for (int i = 2; i <= n; i++) r *= (double)i; return r; }
__device__ __forceinline__ int imax3(int a, int b, int c) { int m = a > b ? a : b; return m > c ? m : c; }
__device__ __forceinline__ int imin3(int a, int b, int c) { int m = a < b ? a : b; return m < c ? m : c; }

__constant__ int cL1[11]  = {0,1,2, 0,1,1,2, 0,1,2,2};
__constant__ int cL2[11]  = {0,1,2, 1,0,2,1, 2,1,0,2};
__constant__ int cLI[11]  = {0,0,0, 1,1,1,1, 2,2,2,2};
__constant__ int cOFF[11] = {0,1,10,35,44,53,98,143,168,213,238};
__constant__ int cCNT[11] = {1,9,25,9,9,45,45,25,45,25,125};
__constant__ int cUOFF[3] = {0,1,10};

__global__ void w3j_init_kernel() {
    __shared__ double Wc[363];
    __shared__ double sUr[35], sUi[35];
    int tid = threadIdx.x;

    if (tid < 3) {
        int l = tid, d = 2 * l + 1;
        double* Ur = sUr + cUOFF[l];
        double* Ui = sUi + cUOFF[l];
        for (int a = 0; a < d * d; a++) { Ur[a] = 0.0; Ui[a] = 0.0; }
        Ur[l * d + l] = 1.0;
        double s = 1.0 / sqrt(2.0);
        for (int m = 1; m <= l; m++) {
            double pm = ((m & 1) ? -1.0 : 1.0);
            Ur[(l + m) * d + (l + m)] = pm * s;
            Ur[(l + m) * d + (l - m)] = s;
            Ui[(l - m) * d + (l - m)] = s;
            Ui[(l - m) * d + (l + m)] = -pm * s;
        }
    }
    __syncthreads();

    if (tid < 363) {
        int e = tid;
        int p = 0;
        while (p < 10 && e >= cOFF[p] + cCNT[p]) p++;
        int le = e - cOFF[p];
        int j1 = cL1[p], j2 = cL2[p], j3 = cLI[p];
        int d2 = 2 * j2 + 1, d3 = 2 * j3 + 1;
        int c = le % d3, b = (le / d3) % d2, a = le / (d3 * d2);
        int m1 = a - j1, m2 = b - j2, m3 = c - j3;
        double val = 0.0;
        if (m1 + m2 + m3 == 0) {
            double tri = dfac(j1 + j2 - j3) * dfac(j1 - j2 + j3) * dfac(-j1 + j2 + j3)
                       / dfac(j1 + j2 + j3 + 1);
            double pref = sqrt(tri * dfac(j1 + m1) * dfac(j1 - m1) * dfac(j2 + m2)
                               * dfac(j2 - m2) * dfac(j3 + m3) * dfac(j3 - m3));
            int t0 = imax3(0, j2 - j3 - m1, j1 - j3 + m2);
            int t1 = imin3(j1 + j2 - j3, j1 - m1, j2 + m2);
            double s = 0.0;
            for (int t = t0; t <= t1; t++) {
                double den = dfac(t) * dfac(j1 + j2 - j3 - t) * dfac(j1 - m1 - t)
                           * dfac(j2 + m2 - t) * dfac(j3 - j2 + m1 + t) * dfac(j3 - j1 - m2 + t);
                s += ((t & 1) ? -1.0 : 1.0) / den;
            }
            double sign = (((j1 - j2 - m3) & 1) ? -1.0 : 1.0);
            val = sign * pref * s;
        }
        Wc[e] = val;
    }
    __syncthreads();

    if (tid < 363) {
        int e = tid;
        int p = 0;
        while (p < 10 && e >= cOFF[p] + cCNT[p]) p++;
        int le = e - cOFF[p];
        int j1 = cL1[p], j2 = cL2[p], j3 = cLI[p];
        int d1 = 2 * j1 + 1, d2 = 2 * j2 + 1, d3 = 2 * j3 + 1;
        int k = le % d3, j = (le / d3) % d2, i = le / (d3 * d2);
        const double* U1r = sUr + cUOFF[j1]; const double* U1i = sUi + cUOFF[j1];
        const double* U2r = sUr + cUOFF[j2]; const double* U2i = sUi + cUOFF[j2];
        const double* U3r = sUr + cUOFF[j3]; const double* U3i = sUi + cUOFF[j3];
        const double* Wp = Wc + cOFF[p];
        double re = 0.0;
        for (int m = 0; m < d1; m++) {
            double u1r = U1r[i * d1 + m], u1i = U1i[i * d1 + m];
            if (u1r == 0.0 && u1i == 0.0) continue;
            for (int nn = 0; nn < d2; nn++) {
                double u2r = U2r[j * d2 + nn], u2i = U2i[j * d2 + nn];
                if (u2r == 0.0 && u2i == 0.0) continue;
                double ar = u1r * u2r - u1i * u2i;
                double ai = u1r * u2i + u1i * u2r;
                for (int pp = 0; pp < d3; pp++) {
                    double w = Wp[(m * d2 + nn) * d3 + pp];
                    if (w == 0.0) continue;
                    re += (ar * U3r[k * d3 + pp] - ai * U3i[k * d3 + pp]) * w;
                }
            }
        }
        g_w3j[e] = (float)re;
    }
}

// ---------------- column permutation ----------------
__global__ __launch_bounds__(256) void permute_kernel(
    const float* __restrict__ w2w, const float* __restrict__ b2w) {
    int t = blockIdx.x * 256 + threadIdx.x;
    if (t >= NPW) return;
    int p = 0;
    while (p < 10 && t >= pOFF[p + 1]) p++;
    int off = pOFF[p], UV = pUV[p];
    int l = t - off;
    int w_hi = l / (UV * 8);
    int rem = l % (UV * 8);
    int uv = rem >> 3, w_lo = rem & 7;
    int ref = off + (w_hi * 8 + w_lo) * UV + uv;
    g_b2wt[t] = b2w[ref];
    #pragma unroll 4
    for (int h = 0; h < HID; h++)
        g_w2wt[h * NPW + t] = w2w[h * NPW + ref];
}

// ---------------- hidden layers: 8 nodes per block ----------------
#define HNODES 8
__global__ __launch_bounds__(128) void hidden_kernel(
    const float* __restrict__ embed,
    const float* __restrict__ w1w, const float* __restrict__ b1w,
    const float* __restrict__ w1b, const float* __restrict__ b1b) {
    __shared__ float se[HNODES][NODE_D];
    int n0 = blockIdx.x * HNODES, tid = threadIdx.x;
    #pragma unroll
    for (int it = 0; it < HNODES; it++) {
        int i = tid + it * 128;
        se[i >> 7][i & 127] = embed[(n0 + (i >> 7)) * NODE_D + (i & 127)];
    }
    __syncthreads();
    int t = tid & 63;
    const float* wmat = (tid < 64) ? w1w : w1b;
    const float* bvec = (tid < 64) ? b1w : b1b;
    float* gout = (tid < 64) ? g_H : g_G;
    float b = bvec[t];
    float acc[HNODES];
    #pragma unroll
    for (int n = 0; n < HNODES; n++) acc[n] = b;
    #pragma unroll 4
    for (int h = 0; h < NODE_D; h++) {
        float w = wmat[h * HID + t];
        #pragma unroll
        for (int n = 0; n < HNODES; n++) acc[n] += se[n][h] * w;
    }
    #pragma unroll
    for (int n = 0; n < HNODES; n++) {
        float a = acc[n];
        gout[(n0 + n) * HID + t] = a / (1.0f + expf(-a));
    }
}

// ---------------- bias: 16 nodes per block ----------------
#define BNODES 16
__global__ __launch_bounds__(352) void bias_kernel(
    const float* __restrict__ w2b, const float* __restrict__ b2b) {
    __shared__ float sg[BNODES][HID];
    int n0 = blockIdx.x * BNODES, tid = threadIdx.x;
    for (int i = tid; i < BNODES * HID; i += 352)
        sg[i >> 6][i & 63] = g_G[(n0 + (i >> 6)) * HID + (i & 63)];
    __syncthreads();
    if (tid < NB) {
        float b = b2b[tid];
        float acc[BNODES];
        #pragma unroll
        for (int n = 0; n < BNODES; n++) acc[n] = b;
        #pragma unroll 4
        for (int h = 0; h < HID; h++) {
            float w = w2b[h * NB + tid];
            #pragma unroll
            for (int n = 0; n < BNODES; n++) acc[n] += sg[n][h] * w;
        }
        #pragma unroll
        for (int n = 0; n < BNODES; n++) g_bias[(n0 + n) * NB + tid] = acc[n];
    }
}

// ---------------- fp16 mma.sync GEMM with ldmatrix (R11, chunked) ----------------
#define SAH 72    // As halfs per row (144B rows)
#define SBH 136   // Bs halfs per row (272B rows)
#define GH_A    0
#define GH_B    (128 * SAH * 2)            // 18432
#define GH_BIAS (GH_B + 64 * SBH * 2)      // 35840
#define GH_TOT  (GH_BIAS + 512)            // 36352

__global__ __launch_bounds__(256, 2) void gemm_mma_kernel(int m_base) {
    extern __shared__ char smem[];
    __half* As = (__half*)(smem + GH_A);
    __half* Bs = (__half*)(smem + GH_B);
    float* bsm = (float*)(smem + GH_BIAS);

    int tid = threadIdx.x;
    int wid = tid >> 5, lane = tid & 31;
    int m0 = m_base + blockIdx.y * 128;
    int n0 = blockIdx.x * 128;

    if (tid < 128) bsm[tid] = g_b2wt[n0 + tid];

    #pragma unroll
    for (int it = 0; it < 8; it++) {
        int i = tid + it * 256;
        int m = i >> 4, k4 = (i & 15) * 4;
        float4 v = *(const float4*)&g_H[(m0 + m) * HID + k4];
        __half2 h0 = __floats2half2_rn(v.x, v.y);
        __half2 h1 = __floats2half2_rn(v.z, v.w);
        uint2 pk;
        pk.x = *(uint32_t*)&h0; pk.y = *(uint32_t*)&h1;
        *(uint2*)&As[m * SAH + k4] = pk;
    }
    #pragma unroll
    for (int it = 0; it < 8; it++) {
        int i = tid + it * 256;
        int k = i >> 5, n4 = (i & 31) * 4;
        float4 v = *(const float4*)&g_w2wt[k * NPW + n0 + n4];
        __half2 h0 = __floats2half2_rn(v.x, v.y);
        __half2 h1 = __floats2half2_rn(v.z, v.w);
        uint2 pk;
        pk.x = *(uint32_t*)&h0; pk.y = *(uint32_t*)&h1;
        *(uint2*)&Bs[k * SBH + n4] = pk;
    }
    __syncthreads();

    int wm = (wid >> 1) * 32;
    int wn = (wid & 1) * 64;
    int lr = lane >> 2;
    int lc = lane & 3;

    uint32_t sA = smem_u32(As);
    uint32_t sB = smem_u32(Bs);
    int l15 = lane & 15, lhi = lane >> 4;
    uint32_t aAddr0 = sA + (uint32_t)(((wm + l15) * SAH + 8 * lhi) * 2);
    uint32_t aAddr1 = aAddr0 + (uint32_t)(16 * SAH * 2);
    uint32_t bAddrBase = sB + (uint32_t)((l15 * SBH + wn + 8 * lhi) * 2);

    float acc[2][8][4];
    #pragma unroll
    for (int mi = 0; mi < 2; mi++)
        #pragma unroll
        for (int f = 0; f < 8; f++)
            #pragma unroll
            for (int c = 0; c < 4; c++) acc[mi][f][c] = 0.0f;

    #pragma unroll
    for (int k0 = 0; k0 < HID; k0 += 16) {
        uint32_t a[2][4];
        asm volatile("ldmatrix.sync.aligned.m8n8.x4.shared.b16 {%0,%1,%2,%3}, [%4];"
            : "=r"(a[0][0]), "=r"(a[0][1]), "=r"(a[0][2]), "=r"(a[0][3])
            : "r"(aAddr0 + (uint32_t)(k0 * 2)));
        asm volatile("ldmatrix.sync.aligned.m8n8.x4.shared.b16 {%0,%1,%2,%3}, [%4];"
            : "=r"(a[1][0]), "=r"(a[1][1]), "=r"(a[1][2]), "=r"(a[1][3])
            : "r"(aAddr1 + (uint32_t)(k0 * 2)));
        uint32_t b[4][4];
        #pragma unroll
        for (int fp = 0; fp < 4; fp++) {
            asm volatile("ldmatrix.sync.aligned.m8n8.x4.trans.shared.b16 {%0,%1,%2,%3}, [%4];"
                : "=r"(b[fp][0]), "=r"(b[fp][1]), "=r"(b[fp][2]), "=r"(b[fp][3])
                : "r"(bAddrBase + (uint32_t)((k0 * SBH + fp * 16) * 2)));
        }
        #pragma unroll
        for (int mi = 0; mi < 2; mi++) {
            #pragma unroll
            for (int f = 0; f < 8; f++) {
                int fp = f >> 1, j = f & 1;
                asm volatile(
                    "mma.sync.aligned.m16n8k16.row.col.f32.f16.f16.f32 "
                    "{%0,%1,%2,%3}, {%4,%5,%6,%7}, {%8,%9}, {%0,%1,%2,%3};"
                    : "+f"(acc[mi][f][0]), "+f"(acc[mi][f][1]),
                      "+f"(acc[mi][f][2]), "+f"(acc[mi][f][3])
                    : "r"(a[mi][0]), "r"(a[mi][1]), "r"(a[mi][2]), "r"(a[mi][3]),
                      "r"(b[fp][2 * j]), "r"(b[fp][2 * j + 1]));
            }
        }
    }

    __syncthreads();
    __half2* stg2 = (__half2*)smem;
    #pragma unroll
    for (int mi = 0; mi < 2; mi++) {
        int r = wm + mi * 16 + lr;
        #pragma unroll
        for (int f = 0; f < 8; f++) {
            int col = wn + f * 8 + 2 * lc;
            float b0 = bsm[col], b1 = bsm[col + 1];
            int c2 = (col >> 1);
            stg2[r * 68 + c2]       = __floats2half2_rn(acc[mi][f][0] + b0, acc[mi][f][1] + b1);
            stg2[(r + 8) * 68 + c2] = __floats2half2_rn(acc[mi][f][2] + b0, acc[mi][f][3] + b1);
        }
    }
    __syncthreads();
    const __half* stg = (const __half*)smem;
    #pragma unroll
    for (int it = 0; it < 8; it++) {
        int i = tid + it * 256;
        int r = i >> 4, q = i & 15;
        uint4 v = *(const uint4*)&stg[r * 136 + q * 8];
        *(uint4*)&g_weight_h[(size_t)(m0 + r) * NPW + n0 + q * 8] = v;
    }
}

// ---------------- per-node expansion: permuted layout, uint4 weight loads (chunked) ----------------
template<int MUL_IN, int MUL1, int MUL2, int D1, int D2, int DI,
         int W_OFF, int B_OFF, int W3J_OFF, int ROW_OFF, int COL_OFF, int X_OFF, bool ACCUM>
__device__ __forceinline__ void path_fn(int lid, const __half* __restrict__ wrow,
                                        const float* xsh, const float* bsh,
                                        const float* w3s, float* osh) {
    constexpr int UV = MUL1 * MUL2;
    int u = lid / MUL2, v = lid % MUL2;
    float res[DI];
    #pragma unroll
    for (int k = 0; k < DI; k++) res[k] = 0.0f;
    const __half* wp = wrow + W_OFF + lid * 8;
    #pragma unroll
    for (int wh = 0; wh < MUL_IN / 8; wh++) {
        uint4 q = *(const uint4*)&wp[wh * UV * 8];
        uint32_t qq[4] = {q.x, q.y, q.z, q.w};
        #pragma unroll
        for (int pp = 0; pp < 4; pp++) {
            float2 f = __half22float2(*(__half2*)&qq[pp]);
            int w = wh * 8 + pp * 2;
            #pragma unroll
            for (int k = 0; k < DI; k++) {
                res[k] += f.x * xsh[X_OFF + w * DI + k];
                res[k] += f.y * xsh[X_OFF + (w + 1) * DI + k];
            }
        }
    }
    if (B_OFF >= 0) res[0] += bsh[B_OFF + lid];
    constexpr float inv = 1.0f / (float)MUL_IN;
    #pragma unroll
    for (int a = 0; a < D1; a++) {
        #pragma unroll
        for (int b = 0; b < D2; b++) {
            float acc = 0.0f;
            #pragma unroll
            for (int k = 0; k < DI; k++)
                acc += w3s[W3J_OFF + (a * D2 + b) * DI + k] * res[k];
            float* o = &osh[(ROW_OFF + u * D1 + a) * OUTD + COL_OFF + v * D2 + b];
            if (ACCUM) *o += acc * inv;
            else       *o  = acc * inv;
        }
    }
}

#define ETHREADS 512
__global__ __launch_bounds__(ETHREADS) void expand_kernel(
    const float* __restrict__ x_in, float* __restrict__ out, int n_base) {
    __shared__ float xsh[D_IN];
    __shared__ float bsh[NB];
    __shared__ float w3s[363];
    __shared__ float osh[OUTD * OUTD];
    int n = n_base + blockIdx.x, tid = threadIdx.x;
    const __half* wrow = g_weight_h + (size_t)n * NPW;

    for (int i = tid; i < D_IN; i += ETHREADS) xsh[i] = x_in[n * D_IN + i];
    for (int i = tid; i < NB; i += ETHREADS) bsh[i] = g_bias[n * NB + i];
    for (int i = tid; i < 363; i += ETHREADS) w3s[i] = g_w3j[i];
    for (int i = tid; i < OUTD * OUTD; i += ETHREADS) osh[i] = 0.0f;
    __syncthreads();

    // Wave 1 (large paths)
    //         MUL_IN MUL1 MUL2 D1 D2 DI  W_OFF  B_OFF W3J ROW COL X_OFF ACC
    if (tid < 256) {
        path_fn<32, 16, 16, 1, 1, 1,     0,   0,   0,   0,  0,  0, false>(tid,       wrow, xsh, bsh, w3s, osh);
    } else if (tid < 384) {
        path_fn<16, 16,  8, 1, 3, 3, 10752,  -1,  35,   0, 16, 32, false>(tid - 256, wrow, xsh, bsh, w3s, osh);
    } else {
        path_fn<16,  8, 16, 3, 1, 3, 12800,  -1,  44,  16,  0, 32, false>(tid - 384, wrow, xsh, bsh, w3s, osh);
    }

    // Wave 2 (small paths): disjoint osh elements
    if (tid < 64) {
        path_fn<32,  8,  8, 3, 3, 1,  8192, 256,   1,  16, 16,  0, false>(tid,       wrow, xsh, bsh, w3s, osh);
        path_fn< 8,  8,  8, 3, 3, 5, 16384,  -1, 168,  16, 16, 80, true >(tid,       wrow, xsh, bsh, w3s, osh);
    } else if (tid < 128) {
        path_fn< 8, 16,  4, 1, 5, 5, 15872,  -1, 143,   0, 40, 80, false>(tid - 64,  wrow, xsh, bsh, w3s, osh);
    } else if (tid < 192) {
        path_fn< 8,  4, 16, 5, 1, 5, 16896,  -1, 213,  40,  0, 80, false>(tid - 128, wrow, xsh, bsh, w3s, osh);
    } else if (tid < 224) {
        path_fn<16,  8,  4, 3, 5, 3, 14848,  -1,  53,  16, 40, 32, false>(tid - 192, wrow, xsh, bsh, w3s, osh);
    } else if (tid < 256) {
        path_fn<16,  4,  8, 5, 3, 3, 15360,  -1,  98,  40, 16, 32, false>(tid - 224, wrow, xsh, bsh, w3s, osh);
    } else if (tid < 272) {
        path_fn<32,  4,  4, 5, 5, 1, 10240, 320,  10,  40, 40,  0, false>(tid - 256, wrow, xsh, bsh, w3s, osh);
        path_fn< 8,  4,  4, 5, 5, 5, 17408,  -1, 238,  40, 40, 80, true >(tid - 256, wrow, xsh, bsh, w3s, osh);
    }
    __syncthreads();

    for (int i = tid; i < OUTD * OUTD; i += ETHREADS)
        out[(size_t)n * (OUTD * OUTD) + i] = osh[i];
}

// ---------------- launch ----------------
extern "C" void kernel_launch(void* const* d_in, const int* in_sizes, int n_in,
                              void* d_out, int out_size) {
    const float* x_in  = (const float*)d_in[0];
    const float* embed = (const float*)d_in[1];
    const float* w1w   = (const float*)d_in[2];
    const float* b1w   = (const float*)d_in[3];
    const float* w2w   = (const float*)d_in[4];
    const float* b2w   = (const float*)d_in[5];
    const float* w1b   = (const float*)d_in[6];
    const float* b1b   = (const float*)d_in[7];
    const float* w2b   = (const float*)d_in[8];
    const float* b2b   = (const float*)d_in[9];
    float* out = (float*)d_out;

    cudaFuncSetAttribute(gemm_mma_kernel, cudaFuncAttributeMaxDynamicSharedMemorySize, GH_TOT);

    w3j_init_kernel<<<1, 384>>>();
    permute_kernel<<<(NPW + 255) / 256, 256>>>(w2w, b2w);
    hidden_kernel<<<NN / HNODES, 128>>>(embed, w1w, b1w, w1b, b1b);
    bias_kernel<<<NN / BNODES, 352>>>(w2b, b2b);

    for (int c = 0; c < NCHUNK; c++) {
        gemm_mma_kernel<<<dim3(NPW / 128, CHN / 128), 256, GH_TOT>>>(c * CHN);
        expand_kernel<<<CHN, ETHREADS>>>(x_in, out, c * CHN);
    }
}

// round 15
// speedup vs baseline: 1.0912x; 1.0912x over previous
#include <cuda_runtime.h>
#include <cuda_fp16.h>
#include <math.h>
#include <stdint.h>

// ---------------- problem constants ----------------
#define NN       8192
#define D_IN     120
#define NODE_D   128
#define HID      64
#define NPW      17536     // num path weights
#define NB       336       // num bias
#define OUTD     60        // out is [N, 60, 60]

// scratch (device globals: allocation-free rule)
__device__ float  g_H[NN * HID];
__device__ float  g_G[NN * HID];
__device__ float  g_bias[NN * NB];
__device__ __half g_weight_h[(size_t)NN * NPW];   // PERMUTED layout [path][w_hi][uv][w_lo=8]
__device__ float  g_w3j[363];
__device__ float  g_w2wt[HID * NPW];              // w2w with permuted columns
__device__ float  g_b2wt[NPW];                    // b2w permuted
__device__ float  g_w2bt[NB * HID];               // w2b transposed [t][h]

__device__ __forceinline__ uint32_t smem_u32(const void* p) {
    uint32_t a;
    asm("{ .reg .u64 t; cvta.to.shared.u64 t, %1; cvt.u32.u64 %0, t; }" : "=r"(a) : "l"(p));
    return a;
}

// ---------------- path tables ----------------
__constant__ int pOFF[12] = {0,8192,10240,10752,12800,14848,15360,15872,16384,16896,17408,17536};
__constant__ int pUV[11]  = {256,64,16,128,128,32,32,64,64,64,16};

// ---------------- Wigner 3j init (parallel, fp64, mirrors reference) ----------------
__device__ double dfac(int n) { double r = 1.0; for (int i = 2; i <= n; i++) r *= (double)i; return r; }
__device__ __forceinline__ int imax3(int a, int b, int c) { int m = a > b ? a : b; return m > c ? m : c; }
__device__ __forceinline__ int imin3(int a, int b, int c) { int m = a < b ? a : b; return m < c ? m : c; }

__constant__ int cL1[11]  = {0,1,2, 0,1,1,2, 0,1,2,2};
__constant__ int cL2[11]  = {0,1,2, 1,0,2,1, 2,1,0,2};
__constant__ int cLI[11]  = {0,0,0, 1,1,1,1, 2,2,2,2};
__constant__ int cOFF[11] = {0,1,10,35,44,53,98,143,168,213,238};
__constant__ int cCNT[11] = {1,9,25,9,9,45,45,25,45,25,125};
__constant__ int cUOFF[3] = {0,1,10};

__global__ void w3j_init_kernel() {
    __shared__ double Wc[363];
    __shared__ double sUr[35], sUi[35];
    int tid = threadIdx.x;

    if (tid < 3) {
        int l = tid, d = 2 * l + 1;
        double* Ur = sUr + cUOFF[l];
        double* Ui = sUi + cUOFF[l];
        for (int a = 0; a < d * d; a++) { Ur[a] = 0.0; Ui[a] = 0.0; }
        Ur[l * d + l] = 1.0;
        double s = 1.0 / sqrt(2.0);
        for (int m = 1; m <= l; m++) {
            double pm = ((m & 1) ? -1.0 : 1.0);
            Ur[(l + m) * d + (l + m)] = pm * s;
            Ur[(l + m) * d + (l - m)] = s;
            Ui[(l - m) * d + (l - m)] = s;
            Ui[(l - m) * d + (l + m)] = -pm * s;
        }
    }
    __syncthreads();

    if (tid < 363) {
        int e = tid;
        int p = 0;
        while (p < 10 && e >= cOFF[p] + cCNT[p]) p++;
        int le = e - cOFF[p];
        int j1 = cL1[p], j2 = cL2[p], j3 = cLI[p];
        int d2 = 2 * j2 + 1, d3 = 2 * j3 + 1;
        int c = le % d3, b = (le / d3) % d2, a = le / (d3 * d2);
        int m1 = a - j1, m2 = b - j2, m3 = c - j3;
        double val = 0.0;
        if (m1 + m2 + m3 == 0) {
            double tri = dfac(j1 + j2 - j3) * dfac(j1 - j2 + j3) * dfac(-j1 + j2 + j3)
                       / dfac(j1 + j2 + j3 + 1);
            double pref = sqrt(tri * dfac(j1 + m1) * dfac(j1 - m1) * dfac(j2 + m2)
                               * dfac(j2 - m2) * dfac(j3 + m3) * dfac(j3 - m3));
            int t0 = imax3(0, j2 - j3 - m1, j1 - j3 + m2);
            int t1 = imin3(j1 + j2 - j3, j1 - m1, j2 + m2);
            double s = 0.0;
            for (int t = t0; t <= t1; t++) {
                double den = dfac(t) * dfac(j1 + j2 - j3 - t) * dfac(j1 - m1 - t)
                           * dfac(j2 + m2 - t) * dfac(j3 - j2 + m1 + t) * dfac(j3 - j1 - m2 + t);
                s += ((t & 1) ? -1.0 : 1.0) / den;
            }
            double sign = (((j1 - j2 - m3) & 1) ? -1.0 : 1.0);
            val = sign * pref * s;
        }
        Wc[e] = val;
    }
    __syncthreads();

    if (tid < 363) {
        int e = tid;
        int p = 0;
        while (p < 10 && e >= cOFF[p] + cCNT[p]) p++;
        int le = e - cOFF[p];
        int j1 = cL1[p], j2 = cL2[p], j3 = cLI[p];
        int d1 = 2 * j1 + 1, d2 = 2 * j2 + 1, d3 = 2 * j3 + 1;
        int k = le % d3, j = (le / d3) % d2, i = le / (d3 * d2);
        const double* U1r = sUr + cUOFF[j1]; const double* U1i = sUi + cUOFF[j1];
        const double* U2r = sUr + cUOFF[j2]; const double* U2i = sUi + cUOFF[j2];
        const double* U3r = sUr + cUOFF[j3]; const double* U3i = sUi + cUOFF[j3];
        const double* Wp = Wc + cOFF[p];
        double re = 0.0;
        for (int m = 0; m < d1; m++) {
            double u1r = U1r[i * d1 + m], u1i = U1i[i * d1 + m];
            if (u1r == 0.0 && u1i == 0.0) continue;
            for (int nn = 0; nn < d2; nn++) {
                double u2r = U2r[j * d2 + nn], u2i = U2i[j * d2 + nn];
                if (u2r == 0.0 && u2i == 0.0) continue;
                double ar = u1r * u2r - u1i * u2i;
                double ai = u1r * u2i + u1i * u2r;
                for (int pp = 0; pp < d3; pp++) {
                    double w = Wp[(m * d2 + nn) * d3 + pp];
                    if (w == 0.0) continue;
                    re += (ar * U3r[k * d3 + pp] - ai * U3i[k * d3 + pp]) * w;
                }
            }
        }
        g_w3j[e] = (float)re;
    }
}

// ---------------- column permutation ----------------
__global__ __launch_bounds__(256) void permute_kernel(
    const float* __restrict__ w2w, const float* __restrict__ b2w) {
    int t = blockIdx.x * 256 + threadIdx.x;
    if (t >= NPW) return;
    int p = 0;
    while (p < 10 && t >= pOFF[p + 1]) p++;
    int off = pOFF[p], UV = pUV[p];
    int l = t - off;
    int w_hi = l / (UV * 8);
    int rem = l % (UV * 8);
    int uv = rem >> 3, w_lo = rem & 7;
    int ref = off + (w_hi * 8 + w_lo) * UV + uv;
    g_b2wt[t] = b2w[ref];
    #pragma unroll 4
    for (int h = 0; h < HID; h++)
        g_w2wt[h * NPW + t] = w2w[h * NPW + ref];
}

// ---------------- transpose w2b: g_w2bt[t][h] = w2b[h][t] ----------------
__global__ __launch_bounds__(64) void transpose_w2b_kernel(const float* __restrict__ w2b) {
    int t = blockIdx.x, h = threadIdx.x;
    g_w2bt[t * HID + h] = w2b[h * NB + t];
}

// ---------------- hidden layers: 8 nodes per block ----------------
#define HNODES 8
__global__ __launch_bounds__(128) void hidden_kernel(
    const float* __restrict__ embed,
    const float* __restrict__ w1w, const float* __restrict__ b1w,
    const float* __restrict__ w1b, const float* __restrict__ b1b) {
    __shared__ float se[HNODES][NODE_D];
    int n0 = blockIdx.x * HNODES, tid = threadIdx.x;
    #pragma unroll
    for (int it = 0; it < HNODES; it++) {
        int i = tid + it * 128;
        se[i >> 7][i & 127] = embed[(n0 + (i >> 7)) * NODE_D + (i & 127)];
    }
    __syncthreads();
    int t = tid & 63;
    const float* wmat = (tid < 64) ? w1w : w1b;
    const float* bvec = (tid < 64) ? b1w : b1b;
    float* gout = (tid < 64) ? g_H : g_G;
    float b = bvec[t];
    float acc[HNODES];
    #pragma unroll
    for (int n = 0; n < HNODES; n++) acc[n] = b;
    #pragma unroll 4
    for (int h = 0; h < NODE_D; h++) {
        float w = wmat[h * HID + t];
        #pragma unroll
        for (int n = 0; n < HNODES; n++) acc[n] += se[n][h] * w;
    }
    #pragma unroll
    for (int n = 0; n < HNODES; n++) {
        float a = acc[n];
        gout[(n0 + n) * HID + t] = a / (1.0f + expf(-a));
    }
}

// ---------------- bias: float4 both sides, 8 nodes per block ----------------
#define BNODES 8
__global__ __launch_bounds__(352) void bias_kernel(const float* __restrict__ b2b) {
    __shared__ float4 sg4[BNODES][HID / 4];
    int n0 = blockIdx.x * BNODES, tid = threadIdx.x;
    if (tid < BNODES * 16) {
        int n = tid >> 4, h4 = tid & 15;
        sg4[n][h4] = ((const float4*)&g_G[(n0 + n) * HID])[h4];
    }
    __syncthreads();
    if (tid < NB) {
        float b = b2b[tid];
        float acc[BNODES];
        #pragma unroll
        for (int n = 0; n < BNODES; n++) acc[n] = b;
        const float4* wt = (const float4*)&g_w2bt[tid * HID];
        #pragma unroll 4
        for (int h4 = 0; h4 < HID / 4; h4++) {
            float4 w = wt[h4];
            #pragma unroll
            for (int n = 0; n < BNODES; n++) {
                float4 s = sg4[n][h4];
                acc[n] += w.x * s.x + w.y * s.y + w.z * s.z + w.w * s.w;
            }
        }
        #pragma unroll
        for (int n = 0; n < BNODES; n++) g_bias[(n0 + n) * NB + tid] = acc[n];
    }
}

// ---------------- fp16 mma.sync GEMM with ldmatrix (R13, unchanged) ----------------
#define SAH 72
#define SBH 136
#define GH_A    0
#define GH_B    (128 * SAH * 2)
#define GH_BIAS (GH_B + 64 * SBH * 2)
#define GH_TOT  (GH_BIAS + 512)

__global__ __launch_bounds__(256, 2) void gemm_mma_kernel() {
    extern __shared__ char smem[];
    __half* As = (__half*)(smem + GH_A);
    __half* Bs = (__half*)(smem + GH_B);
    float* bsm = (float*)(smem + GH_BIAS);

    int tid = threadIdx.x;
    int wid = tid >> 5, lane = tid & 31;
    int m0 = blockIdx.y * 128;
    int n0 = blockIdx.x * 128;

    if (tid < 128) bsm[tid] = g_b2wt[n0 + tid];

    #pragma unroll
    for (int it = 0; it < 8; it++) {
        int i = tid + it * 256;
        int m = i >> 4, k4 = (i & 15) * 4;
        float4 v = *(const float4*)&g_H[(m0 + m) * HID + k4];
        __half2 h0 = __floats2half2_rn(v.x, v.y);
        __half2 h1 = __floats2half2_rn(v.z, v.w);
        uint2 pk;
        pk.x = *(uint32_t*)&h0; pk.y = *(uint32_t*)&h1;
        *(uint2*)&As[m * SAH + k4] = pk;
    }
    #pragma unroll
    for (int it = 0; it < 8; it++) {
        int i = tid + it * 256;
        int k = i >> 5, n4 = (i & 31) * 4;
        float4 v = *(const float4*)&g_w2wt[k * NPW + n0 + n4];
        __half2 h0 = __floats2half2_rn(v.x, v.y);
        __half2 h1 = __floats2half2_rn(v.z, v.w);
        uint2 pk;
        pk.x = *(uint32_t*)&h0; pk.y = *(uint32_t*)&h1;
        *(uint2*)&Bs[k * SBH + n4] = pk;
    }
    __syncthreads();

    int wm = (wid >> 1) * 32;
    int wn = (wid & 1) * 64;
    int lr = lane >> 2;
    int lc = lane & 3;

    uint32_t sA = smem_u32(As);
    uint32_t sB = smem_u32(Bs);
    int l15 = lane & 15, lhi = lane >> 4;
    uint32_t aAddr0 = sA + (uint32_t)(((wm + l15) * SAH + 8 * lhi) * 2);
    uint32_t aAddr1 = aAddr0 + (uint32_t)(16 * SAH * 2);
    uint32_t bAddrBase = sB + (uint32_t)((l15 * SBH + wn + 8 * lhi) * 2);

    float acc[2][8][4];
    #pragma unroll
    for (int mi = 0; mi < 2; mi++)
        #pragma unroll
        for (int f = 0; f < 8; f++)
            #pragma unroll
            for (int c = 0; c < 4; c++) acc[mi][f][c] = 0.0f;

    #pragma unroll
    for (int k0 = 0; k0 < HID; k0 += 16) {
        uint32_t a[2][4];
        asm volatile("ldmatrix.sync.aligned.m8n8.x4.shared.b16 {%0,%1,%2,%3}, [%4];"
            : "=r"(a[0][0]), "=r"(a[0][1]), "=r"(a[0][2]), "=r"(a[0][3])
            : "r"(aAddr0 + (uint32_t)(k0 * 2)));
        asm volatile("ldmatrix.sync.aligned.m8n8.x4.shared.b16 {%0,%1,%2,%3}, [%4];"
            : "=r"(a[1][0]), "=r"(a[1][1]), "=r"(a[1][2]), "=r"(a[1][3])
            : "r"(aAddr1 + (uint32_t)(k0 * 2)));
        uint32_t b[4][4];
        #pragma unroll
        for (int fp = 0; fp < 4; fp++) {
            asm volatile("ldmatrix.sync.aligned.m8n8.x4.trans.shared.b16 {%0,%1,%2,%3}, [%4];"
                : "=r"(b[fp][0]), "=r"(b[fp][1]), "=r"(b[fp][2]), "=r"(b[fp][3])
                : "r"(bAddrBase + (uint32_t)((k0 * SBH + fp * 16) * 2)));
        }
        #pragma unroll
        for (int mi = 0; mi < 2; mi++) {
            #pragma unroll
            for (int f = 0; f < 8; f++) {
                int fp = f >> 1, j = f & 1;
                asm volatile(
                    "mma.sync.aligned.m16n8k16.row.col.f32.f16.f16.f32 "
                    "{%0,%1,%2,%3}, {%4,%5,%6,%7}, {%8,%9}, {%0,%1,%2,%3};"
                    : "+f"(acc[mi][f][0]), "+f"(acc[mi][f][1]),
                      "+f"(acc[mi][f][2]), "+f"(acc[mi][f][3])
                    : "r"(a[mi][0]), "r"(a[mi][1]), "r"(a[mi][2]), "r"(a[mi][3]),
                      "r"(b[fp][2 * j]), "r"(b[fp][2 * j + 1]));
            }
        }
    }

    __syncthreads();
    __half2* stg2 = (__half2*)smem;
    #pragma unroll
    for (int mi = 0; mi < 2; mi++) {
        int r = wm + mi * 16 + lr;
        #pragma unroll
        for (int f = 0; f < 8; f++) {
            int col = wn + f * 8 + 2 * lc;
            float b0 = bsm[col], b1 = bsm[col + 1];
            int c2 = (col >> 1);
            stg2[r * 68 + c2]       = __floats2half2_rn(acc[mi][f][0] + b0, acc[mi][f][1] + b1);
            stg2[(r + 8) * 68 + c2] = __floats2half2_rn(acc[mi][f][2] + b0, acc[mi][f][3] + b1);
        }
    }
    __syncthreads();
    const __half* stg = (const __half*)smem;
    #pragma unroll
    for (int it = 0; it < 8; it++) {
        int i = tid + it * 256;
        int r = i >> 4, q = i & 15;
        uint4 v = *(const uint4*)&stg[r * 136 + q * 8];
        *(uint4*)&g_weight_h[(size_t)(m0 + r) * NPW + n0 + q * 8] = v;
    }
}

// ---------------- expansion helpers ----------------
// res from permuted layout: weight(w, uv) at W_OFF + w_hi*(UV*8) + uv*8 + w_lo
template<int MUL_IN, int UV, int DI, int X_OFF>
__device__ __forceinline__ void load_res(const __half* __restrict__ wp,
                                         const float* xsh, float* res) {
    #pragma unroll
    for (int k = 0; k < DI; k++) res[k] = 0.0f;
    #pragma unroll
    for (int wh = 0; wh < MUL_IN / 8; wh++) {
        uint4 q = *(const uint4*)&wp[wh * UV * 8];
        uint32_t qq[4] = {q.x, q.y, q.z, q.w};
        #pragma unroll
        for (int pp = 0; pp < 4; pp++) {
            float2 f = __half22float2(*(__half2*)&qq[pp]);
            int w = wh * 8 + pp * 2;
            #pragma unroll
            for (int k = 0; k < DI; k++) {
                res[k] += f.x * xsh[X_OFF + w * DI + k];
                res[k] += f.y * xsh[X_OFF + (w + 1) * DI + k];
            }
        }
    }
}

// full path (all outputs, write)
template<int MUL_IN, int MUL1, int MUL2, int D1, int D2, int DI,
         int W_OFF, int B_OFF, int W3J_OFF, int ROW_OFF, int COL_OFF, int X_OFF>
__device__ __forceinline__ void path_fn(int lid, const __half* __restrict__ wrow,
                                        const float* xsh, const float* bsh,
                                        const float* w3s, float* osh) {
    constexpr int UV = MUL1 * MUL2;
    int u = lid / MUL2, v = lid % MUL2;
    float res[DI];
    load_res<MUL_IN, UV, DI, X_OFF>(wrow + W_OFF + lid * 8, xsh, res);
    if (B_OFF >= 0) res[0] += bsh[B_OFF + lid];
    constexpr float inv = 1.0f / (float)MUL_IN;
    #pragma unroll
    for (int ab = 0; ab < D1 * D2; ab++) {
        int a = ab / D2, b = ab % D2;
        float acc = 0.0f;
        #pragma unroll
        for (int k = 0; k < DI; k++)
            acc += w3s[W3J_OFF + ab * DI + k] * res[k];
        osh[(ROW_OFF + u * D1 + a) * OUTD + COL_OFF + v * D2 + b] = acc * inv;
    }
}

// single path, output-split NSPLIT ways (write)
template<int MUL_IN, int MUL1, int MUL2, int D1, int D2, int DI,
         int W_OFF, int W3J_OFF, int ROW_OFF, int COL_OFF, int X_OFF, int NSPLIT>
__device__ __forceinline__ void path_split(int uv, int split, const __half* __restrict__ wrow,
                                           const float* xsh, const float* w3s, float* osh) {
    constexpr int UV = MUL1 * MUL2;
    int u = uv / MUL2, v = uv % MUL2;
    float res[DI];
    load_res<MUL_IN, UV, DI, X_OFF>(wrow + W_OFF + uv * 8, xsh, res);
    constexpr float inv = 1.0f / (float)MUL_IN;
    #pragma unroll
    for (int ab = split; ab < D1 * D2; ab += NSPLIT) {
        int a = ab / D2, b = ab % D2;
        float acc = 0.0f;
        #pragma unroll
        for (int k = 0; k < DI; k++)
            acc += w3s[W3J_OFF + ab * DI + k] * res[k];
        osh[(ROW_OFF + u * D1 + a) * OUTD + COL_OFF + v * D2 + b] = acc * inv;
    }
}

// merged pair (A + B share output block), output-split NSPLIT ways (write)
template<int MI_A, int DI_A, int W_A, int B_A, int W3_A, int XO_A,
         int MI_B, int DI_B, int W_B, int W3_B, int XO_B,
         int MUL1, int MUL2, int D1, int D2, int ROW_OFF, int COL_OFF, int NSPLIT>
__device__ __forceinline__ void path_pair(int uv, int split, const __half* __restrict__ wrow,
                                          const float* xsh, const float* bsh,
                                          const float* w3s, float* osh) {
    constexpr int UV = MUL1 * MUL2;
    int u = uv / MUL2, v = uv % MUL2;
    float ra[DI_A], rb[DI_B];
    load_res<MI_A, UV, DI_A, XO_A>(wrow + W_A + uv * 8, xsh, ra);
    if (B_A >= 0) ra[0] += bsh[B_A + uv];
    load_res<MI_B, UV, DI_B, XO_B>(wrow + W_B + uv * 8, xsh, rb);
    constexpr float invA = 1.0f / (float)MI_A;
    constexpr float invB = 1.0f / (float)MI_B;
    #pragma unroll
    for (int ab = split; ab < D1 * D2; ab += NSPLIT) {
        int a = ab / D2, b = ab % D2;
        float aA = 0.0f;
        #pragma unroll
        for (int k = 0; k < DI_A; k++) aA += w3s[W3_A + ab * DI_A + k] * ra[k];
        float aB = 0.0f;
        #pragma unroll
        for (int k = 0; k < DI_B; k++) aB += w3s[W3_B + ab * DI_B + k] * rb[k];
        osh[(ROW_OFF + u * D1 + a) * OUTD + COL_OFF + v * D2 + b] = aA * invA + aB * invB;
    }
}

#define ETHREADS 512
__global__ __launch_bounds__(ETHREADS) void expand_kernel(
    const float* __restrict__ x_in, float* __restrict__ out) {
    __shared__ float xsh[D_IN];
    __shared__ float bsh[NB];
    __shared__ float w3s[363];
    __shared__ float osh[OUTD * OUTD];
    int n = blockIdx.x, tid = threadIdx.x;
    const __half* wrow = g_weight_h + (size_t)n * NPW;

    for (int i = tid; i < D_IN; i += ETHREADS) xsh[i] = x_in[n * D_IN + i];
    for (int i = tid; i < NB; i += ETHREADS) bsh[i] = g_bias[n * NB + i];
    for (int i = tid; i < 363; i += ETHREADS) w3s[i] = g_w3j[i];
    __syncthreads();

    // Wave 1: large paths (blocks (0,0),(0,1),(1,0))
    //         MUL_IN MUL1 MUL2 D1 D2 DI  W_OFF  B_OFF W3J ROW COL X_OFF
    if (tid < 256) {
        path_fn<32, 16, 16, 1, 1, 1,     0,   0,   0,   0,  0,  0>(tid,       wrow, xsh, bsh, w3s, osh);
    } else if (tid < 384) {
        path_fn<16, 16,  8, 1, 3, 3, 10752,  -1,  35,   0, 16, 32>(tid - 256, wrow, xsh, bsh, w3s, osh);
    } else {
        path_fn<16,  8, 16, 3, 1, 3, 12800,  -1,  44,  16,  0, 32>(tid - 384, wrow, xsh, bsh, w3s, osh);
    }

    // Wave 2: remaining blocks, warp-uniform, balanced (no sync: disjoint outputs)
    if (tid < 128) {
        // W0-3: merged p2+p9 -> block (1,1), split 2
        path_pair<32, 1,  8192, 256,   1,  0,
                   8, 5, 16384,      168, 80,
                   8, 8, 3, 3, 16, 16, 2>(tid >> 1, tid & 1, wrow, xsh, bsh, w3s, osh);
    } else if (tid < 192) {
        // W4-5: merged p3+p11 -> block (2,2), split 4
        int t = tid - 128;
        path_pair<32, 1, 10240, 320,  10,  0,
                   8, 5, 17408,      238, 80,
                   4, 4, 5, 5, 40, 40, 4>(t >> 2, t & 3, wrow, xsh, bsh, w3s, osh);
    } else if (tid < 256) {
        // W6-7: p8 -> block (0,2)
        path_fn< 8, 16,  4, 1, 5, 5, 15872,  -1, 143,   0, 40, 80>(tid - 192, wrow, xsh, bsh, w3s, osh);
    } else if (tid < 320) {
        // W8-9: p10 -> block (2,0)
        path_fn< 8,  4, 16, 5, 1, 5, 16896,  -1, 213,  40,  0, 80>(tid - 256, wrow, xsh, bsh, w3s, osh);
    } else if (tid < 384) {
        // W10-11: p6 split 2 -> block (1,2)
        int t = tid - 320;
        path_split<16,  8,  4, 3, 5, 3, 14848,  53, 16, 40, 32, 2>(t >> 1, t & 1, wrow, xsh, w3s, osh);
    } else if (tid < 448) {
        // W12-13: p7 split 2 -> block (2,1)
        int t = tid - 384;
        path_split<16,  4,  8, 5, 3, 3, 15360,  98, 40, 16, 32, 2>(t >> 1, t & 1, wrow, xsh, w3s, osh);
    }
    __syncthreads();

    for (int i = tid; i < OUTD * OUTD; i += ETHREADS)
        out[(size_t)n * (OUTD * OUTD) + i] = osh[i];
}

// ---------------- launch ----------------
extern "C" void kernel_launch(void* const* d_in, const int* in_sizes, int n_in,
                              void* d_out, int out_size) {
    const float* x_in  = (const float*)d_in[0];
    const float* embed = (const float*)d_in[1];
    const float* w1w   = (const float*)d_in[2];
    const float* b1w   = (const float*)d_in[3];
    const float* w2w   = (const float*)d_in[4];
    const float* b2w   = (const float*)d_in[5];
    const float* w1b   = (const float*)d_in[6];
    const float* b1b   = (const float*)d_in[7];
    const float* w2b   = (const float*)d_in[8];
    const float* b2b   = (const float*)d_in[9];
    float* out = (float*)d_out;

    cudaFuncSetAttribute(gemm_mma_kernel, cudaFuncAttributeMaxDynamicSharedMemorySize, GH_TOT);

    w3j_init_kernel<<<1, 384>>>();
    permute_kernel<<<(NPW + 255) / 256, 256>>>(w2w, b2w);
    transpose_w2b_kernel<<<NB, 64>>>(w2b);
    hidden_kernel<<<NN / HNODES, 128>>>(embed, w1w, b1w, w1b, b1b);
    bias_kernel<<<NN / BNODES, 352>>>(b2b);
    gemm_mma_kernel<<<dim3(NPW / 128, NN / 128), 256, GH_TOT>>>();
    expand_kernel<<<NN, ETHREADS>>>(x_in, out);
}

// round 17
// speedup vs baseline: 1.1206x; 1.0270x over previous
#include <cuda_runtime.h>
#include <cuda_fp16.h>
#include <math.h>
#include <stdint.h>

// ---------------- problem constants ----------------
#define NN       8192
#define D_IN     120
#define NODE_D   128
#define HID      64
#define NPW      17536     // num path weights
#define NB       336       // num bias
#define OUTD     60        // out is [N, 60, 60]

// scratch (device globals: allocation-free rule). 16B-aligned: vector accesses.
__device__ __align__(16) __half g_H_h[NN * HID];                // hidden (weight branch), fp16
__device__ __align__(16) float  g_G[NN * HID];
__device__ __align__(16) float  g_bias[NN * NB];
__device__ __align__(16) __half g_weight_h[(size_t)NN * NPW];   // PERMUTED [path][w_hi][uv][w_lo=8]
__device__ __align__(16) float  g_w3j[363];
__device__ __align__(16) __half g_w2wt_h[HID * NPW];            // w2w permuted columns, fp16
__device__ __align__(16) float  g_b2wt[NPW];                    // b2w permuted
__device__ __align__(16) float  g_w2bt[NB * HID];               // w2b transposed [t][h]

__device__ __forceinline__ uint32_t smem_u32(const void* p) {
    uint32_t a;
    asm("{ .reg .u64 t; cvta.to.shared.u64 t, %1; cvt.u32.u64 %0, t; }" : "=r"(a) : "l"(p));
    return a;
}

// ---------------- path tables ----------------
__constant__ int pOFF[12] = {0,8192,10240,10752,12800,14848,15360,15872,16384,16896,17408,17536};
__constant__ int pUV[11]  = {256,64,16,128,128,32,32,64,64,64,16};

// ---------------- Wigner 3j init (parallel, fp64, mirrors reference) ----------------
__device__ double dfac(int n) { double r = 1.0; for (int i = 2; i <= n; i++) r *= (double)i; return r; }
__device__ __forceinline__ int imax3(int a, int b, int c) { int m = a > b ? a : b; return m > c ? m : c; }
__device__ __forceinline__ int imin3(int a, int b, int c) { int m = a < b ? a : b; return m < c ? m : c; }

__constant__ int cL1[11]  = {0,1,2, 0,1,1,2, 0,1,2,2};
__constant__ int cL2[11]  = {0,1,2, 1,0,2,1, 2,1,0,2};
__constant__ int cLI[11]  = {0,0,0, 1,1,1,1, 2,2,2,2};
__constant__ int cOFF[11] = {0,1,10,35,44,53,98,143,168,213,238};
__constant__ int cCNT[11] = {1,9,25,9,9,45,45,25,45,25,125};
__constant__ int cUOFF[3] = {0,1,10};

__global__ void w3j_init_kernel() {
    __shared__ double Wc[363];
    __shared__ double sUr[35], sUi[35];
    int tid = threadIdx.x;

    if (tid < 3) {
        int l = tid, d = 2 * l + 1;
        double* Ur = sUr + cUOFF[l];
        double* Ui = sUi + cUOFF[l];
        for (int a = 0; a < d * d; a++) { Ur[a] = 0.0; Ui[a] = 0.0; }
        Ur[l * d + l] = 1.0;
        double s = 1.0 / sqrt(2.0);
        for (int m = 1; m <= l; m++) {
            double pm = ((m & 1) ? -1.0 : 1.0);
            Ur[(l + m) * d + (l + m)] = pm * s;
            Ur[(l + m) * d + (l - m)] = s;
            Ui[(l - m) * d + (l - m)] = s;
            Ui[(l - m) * d + (l + m)] = -pm * s;
        }
    }
    __syncthreads();

    if (tid < 363) {
        int e = tid;
        int p = 0;
        while (p < 10 && e >= cOFF[p] + cCNT[p]) p++;
        int le = e - cOFF[p];
        int j1 = cL1[p], j2 = cL2[p], j3 = cLI[p];
        int d2 = 2 * j2 + 1, d3 = 2 * j3 + 1;
        int c = le % d3, b = (le / d3) % d2, a = le / (d3 * d2);
        int m1 = a - j1, m2 = b - j2, m3 = c - j3;
        double val = 0.0;
        if (m1 + m2 + m3 == 0) {
            double tri = dfac(j1 + j2 - j3) * dfac(j1 - j2 + j3) * dfac(-j1 + j2 + j3)
                       / dfac(j1 + j2 + j3 + 1);
            double pref = sqrt(tri * dfac(j1 + m1) * dfac(j1 - m1) * dfac(j2 + m2)
                               * dfac(j2 - m2) * dfac(j3 + m3) * dfac(j3 - m3));
            int t0 = imax3(0, j2 - j3 - m1, j1 - j3 + m2);
            int t1 = imin3(j1 + j2 - j3, j1 - m1, j2 + m2);
            double s = 0.0;
            for (int t = t0; t <= t1; t++) {
                double den = dfac(t) * dfac(j1 + j2 - j3 - t) * dfac(j1 - m1 - t)
                           * dfac(j2 + m2 - t) * dfac(j3 - j2 + m1 + t) * dfac(j3 - j1 - m2 + t);
                s += ((t & 1) ? -1.0 : 1.0) / den;
            }
            double sign = (((j1 - j2 - m3) & 1) ? -1.0 : 1.0);
            val = sign * pref * s;
        }
        Wc[e] = val;
    }
    __syncthreads();

    if (tid < 363) {
        int e = tid;
        int p = 0;
        while (p < 10 && e >= cOFF[p] + cCNT[p]) p++;
        int le = e - cOFF[p];
        int j1 = cL1[p], j2 = cL2[p], j3 = cLI[p];
        int d1 = 2 * j1 + 1, d2 = 2 * j2 + 1, d3 = 2 * j3 + 1;
        int k = le % d3, j = (le / d3) % d2, i = le / (d3 * d2);
        const double* U1r = sUr + cUOFF[j1]; const double* U1i = sUi + cUOFF[j1];
        const double* U2r = sUr + cUOFF[j2]; const double* U2i = sUi + cUOFF[j2];
        const double* U3r = sUr + cUOFF[j3]; const double* U3i = sUi + cUOFF[j3];
        const double* Wp = Wc + cOFF[p];
        double re = 0.0;
        for (int m = 0; m < d1; m++) {
            double u1r = U1r[i * d1 + m], u1i = U1i[i * d1 + m];
            if (u1r == 0.0 && u1i == 0.0) continue;
            for (int nn = 0; nn < d2; nn++) {
                double u2r = U2r[j * d2 + nn], u2i = U2i[j * d2 + nn];
                if (u2r == 0.0 && u2i == 0.0) continue;
                double ar = u1r * u2r - u1i * u2i;
                double ai = u1r * u2i + u1i * u2r;
                for (int pp = 0; pp < d3; pp++) {
                    double w = Wp[(m * d2 + nn) * d3 + pp];
                    if (w == 0.0) continue;
                    re += (ar * U3r[k * d3 + pp] - ai * U3i[k * d3 + pp]) * w;
                }
            }
        }
        g_w3j[e] = (float)re;
    }
}

// ---------------- column permutation (fp16 output) ----------------
__global__ __launch_bounds__(256) void permute_kernel(
    const float* __restrict__ w2w, const float* __restrict__ b2w) {
    int t = blockIdx.x * 256 + threadIdx.x;
    if (t >= NPW) return;
    int p = 0;
    while (p < 10 && t >= pOFF[p + 1]) p++;
    int off = pOFF[p], UV = pUV[p];
    int l = t - off;
    int w_hi = l / (UV * 8);
    int rem = l % (UV * 8);
    int uv = rem >> 3, w_lo = rem & 7;
    int ref = off + (w_hi * 8 + w_lo) * UV + uv;
    g_b2wt[t] = b2w[ref];
    #pragma unroll 4
    for (int h = 0; h < HID; h++)
        g_w2wt_h[h * NPW + t] = __float2half_rn(w2w[h * NPW + ref]);
}

// ---------------- transpose w2b ----------------
__global__ __launch_bounds__(64) void transpose_w2b_kernel(const float* __restrict__ w2b) {
    int t = blockIdx.x, h = threadIdx.x;
    g_w2bt[t * HID + h] = w2b[h * NB + t];
}

// ---------------- hidden layers: 16 nodes per block, H as fp16 ----------------
#define HNODES 16
__global__ __launch_bounds__(128) void hidden_kernel(
    const float* __restrict__ embed,
    const float* __restrict__ w1w, const float* __restrict__ b1w,
    const float* __restrict__ w1b, const float* __restrict__ b1b) {
    __shared__ float se[HNODES][NODE_D];
    int n0 = blockIdx.x * HNODES, tid = threadIdx.x;
    #pragma unroll
    for (int it = 0; it < HNODES; it++) {
        int i = tid + it * 128;
        se[i >> 7][i & 127] = embed[(n0 + (i >> 7)) * NODE_D + (i & 127)];
    }
    __syncthreads();
    int t = tid & 63;
    const float* wmat = (tid < 64) ? w1w : w1b;
    const float* bvec = (tid < 64) ? b1w : b1b;
    float b = bvec[t];
    float acc[HNODES];
    #pragma unroll
    for (int n = 0; n < HNODES; n++) acc[n] = b;
    #pragma unroll 4
    for (int h = 0; h < NODE_D; h++) {
        float w = wmat[h * HID + t];
        #pragma unroll
        for (int n = 0; n < HNODES; n++) acc[n] += se[n][h] * w;
    }
    if (tid < 64) {
        #pragma unroll
        for (int n = 0; n < HNODES; n++) {
            float a = acc[n];
            g_H_h[(n0 + n) * HID + t] = __float2half_rn(a / (1.0f + expf(-a)));
        }
    } else {
        #pragma unroll
        for (int n = 0; n < HNODES; n++) {
            float a = acc[n];
            g_G[(n0 + n) * HID + t] = a / (1.0f + expf(-a));
        }
    }
}

// ---------------- bias: float4 both sides, 8 nodes per block ----------------
#define BNODES 8
__global__ __launch_bounds__(352) void bias_kernel(const float* __restrict__ b2b) {
    __shared__ float4 sg4[BNODES][HID / 4];
    int n0 = blockIdx.x * BNODES, tid = threadIdx.x;
    if (tid < BNODES * 16) {
        int n = tid >> 4, h4 = tid & 15;
        sg4[n][h4] = ((const float4*)&g_G[(n0 + n) * HID])[h4];
    }
    __syncthreads();
    if (tid < NB) {
        float b = b2b[tid];
        float acc[BNODES];
        #pragma unroll
        for (int n = 0; n < BNODES; n++) acc[n] = b;
        const float4* wt = (const float4*)&g_w2bt[tid * HID];
        #pragma unroll 4
        for (int h4 = 0; h4 < HID / 4; h4++) {
            float4 w = wt[h4];
            #pragma unroll
            for (int n = 0; n < BNODES; n++) {
                float4 s = sg4[n][h4];
                acc[n] += w.x * s.x + w.y * s.y + w.z * s.z + w.w * s.w;
            }
        }
        #pragma unroll
        for (int n = 0; n < BNODES; n++) g_bias[(n0 + n) * NB + tid] = acc[n];
    }
}

// ---------------- fp16 mma.sync GEMM with ldmatrix (fp16 staging, no cvt) ----------------
#define SAH 72    // As halfs per row (144B rows)
#define SBH 136   // Bs halfs per row (272B rows)
#define GH_A    0
#define GH_B    (128 * SAH * 2)            // 18432
#define GH_BIAS (GH_B + 64 * SBH * 2)      // 35840
#define GH_TOT  (GH_BIAS + 512)            // 36352

__global__ __launch_bounds__(256, 2) void gemm_mma_kernel() {
    extern __shared__ char smem[];
    __half* As = (__half*)(smem + GH_A);
    __half* Bs = (__half*)(smem + GH_B);
    float* bsm = (float*)(smem + GH_BIAS);

    int tid = threadIdx.x;
    int wid = tid >> 5, lane = tid & 31;
    int m0 = blockIdx.y * 128;
    int n0 = blockIdx.x * 128;

    if (tid < 128) bsm[tid] = g_b2wt[n0 + tid];

    // stage A: 128x64 halfs = 1024 uint4, direct copy
    #pragma unroll
    for (int it = 0; it < 4; it++) {
        int i = tid + it * 256;
        int m = i >> 3, k8 = (i & 7) * 8;
        uint4 v = *(const uint4*)&g_H_h[(m0 + m) * HID + k8];
        *(uint4*)&As[m * SAH + k8] = v;
    }
    // stage B: 64x128 halfs = 1024 uint4, direct copy
    #pragma unroll
    for (int it = 0; it < 4; it++) {
        int i = tid + it * 256;
        int k = i >> 4, n8 = (i & 15) * 8;
        uint4 v = *(const uint4*)&g_w2wt_h[k * NPW + n0 + n8];
        *(uint4*)&Bs[k * SBH + n8] = v;
    }
    __syncthreads();

    int wm = (wid >> 1) * 32;
    int wn = (wid & 1) * 64;
    int lr = lane >> 2;
    int lc = lane & 3;

    uint32_t sA = smem_u32(As);
    uint32_t sB = smem_u32(Bs);
    int l15 = lane & 15, lhi = lane >> 4;
    uint32_t aAddr0 = sA + (uint32_t)(((wm + l15) * SAH + 8 * lhi) * 2);
    uint32_t aAddr1 = aAddr0 + (uint32_t)(16 * SAH * 2);
    uint32_t bAddrBase = sB + (uint32_t)((l15 * SBH + wn + 8 * lhi) * 2);

    float acc[2][8][4];
    #pragma unroll
    for (int mi = 0; mi < 2; mi++)
        #pragma unroll
        for (int f = 0; f < 8; f++)
            #pragma unroll
            for (int c = 0; c < 4; c++) acc[mi][f][c] = 0.0f;

    #pragma unroll
    for (int k0 = 0; k0 < HID; k0 += 16) {
        uint32_t a[2][4];
        asm volatile("ldmatrix.sync.aligned.m8n8.x4.shared.b16 {%0,%1,%2,%3}, [%4];"
            : "=r"(a[0][0]), "=r"(a[0][1]), "=r"(a[0][2]), "=r"(a[0][3])
            : "r"(aAddr0 + (uint32_t)(k0 * 2)));
        asm volatile("ldmatrix.sync.aligned.m8n8.x4.shared.b16 {%0,%1,%2,%3}, [%4];"
            : "=r"(a[1][0]), "=r"(a[1][1]), "=r"(a[1][2]), "=r"(a[1][3])
            : "r"(aAddr1 + (uint32_t)(k0 * 2)));
        uint32_t b[4][4];
        #pragma unroll
        for (int fp = 0; fp < 4; fp++) {
            asm volatile("ldmatrix.sync.aligned.m8n8.x4.trans.shared.b16 {%0,%1,%2,%3}, [%4];"
                : "=r"(b[fp][0]), "=r"(b[fp][1]), "=r"(b[fp][2]), "=r"(b[fp][3])
                : "r"(bAddrBase + (uint32_t)((k0 * SBH + fp * 16) * 2)));
        }
        #pragma unroll
        for (int mi = 0; mi < 2; mi++) {
            #pragma unroll
            for (int f = 0; f < 8; f++) {
                int fp = f >> 1, j = f & 1;
                asm volatile(
                    "mma.sync.aligned.m16n8k16.row.col.f32.f16.f16.f32 "
                    "{%0,%1,%2,%3}, {%4,%5,%6,%7}, {%8,%9}, {%0,%1,%2,%3};"
                    : "+f"(acc[mi][f][0]), "+f"(acc[mi][f][1]),
                      "+f"(acc[mi][f][2]), "+f"(acc[mi][f][3])
                    : "r"(a[mi][0]), "r"(a[mi][1]), "r"(a[mi][2]), "r"(a[mi][3]),
                      "r"(b[fp][2 * j]), "r"(b[fp][2 * j + 1]));
            }
        }
    }

    __syncthreads();
    __half2* stg2 = (__half2*)smem;
    #pragma unroll
    for (int mi = 0; mi < 2; mi++) {
        int r = wm + mi * 16 + lr;
        #pragma unroll
        for (int f = 0; f < 8; f++) {
            int col = wn + f * 8 + 2 * lc;
            float b0 = bsm[col], b1 = bsm[col + 1];
            int c2 = (col >> 1);
            stg2[r * 68 + c2]       = __floats2half2_rn(acc[mi][f][0] + b0, acc[mi][f][1] + b1);
            stg2[(r + 8) * 68 + c2] = __floats2half2_rn(acc[mi][f][2] + b0, acc[mi][f][3] + b1);
        }
    }
    __syncthreads();
    const __half* stg = (const __half*)smem;
    #pragma unroll
    for (int it = 0; it < 8; it++) {
        int i = tid + it * 256;
        int r = i >> 4, q = i & 15;
        uint4 v = *(const uint4*)&stg[r * 136 + q * 8];
        *(uint4*)&g_weight_h[(size_t)(m0 + r) * NPW + n0 + q * 8] = v;
    }
}

// ---------------- expansion helpers (R15, unchanged) ----------------
template<int MUL_IN, int UV, int DI, int X_OFF>
__device__ __forceinline__ void load_res(const __half* __restrict__ wp,
                                         const float* xsh, float* res) {
    #pragma unroll
    for (int k = 0; k < DI; k++) res[k] = 0.0f;
    #pragma unroll
    for (int wh = 0; wh < MUL_IN / 8; wh++) {
        uint4 q = *(const uint4*)&wp[wh * UV * 8];
        uint32_t qq[4] = {q.x, q.y, q.z, q.w};
        #pragma unroll
        for (int pp = 0; pp < 4; pp++) {
            float2 f = __half22float2(*(__half2*)&qq[pp]);
            int w = wh * 8 + pp * 2;
            #pragma unroll
            for (int k = 0; k < DI; k++) {
                res[k] += f.x * xsh[X_OFF + w * DI + k];
                res[k] += f.y * xsh[X_OFF + (w + 1) * DI + k];
            }
        }
    }
}

template<int MUL_IN, int MUL1, int MUL2, int D1, int D2, int DI,
         int W_OFF, int B_OFF, int W3J_OFF, int ROW_OFF, int COL_OFF, int X_OFF>
__device__ __forceinline__ void path_fn(int lid, const __half* __restrict__ wrow,
                                        const float* xsh, const float* bsh,
                                        const float* w3s, float* osh) {
    constexpr int UV = MUL1 * MUL2;
    int u = lid / MUL2, v = lid % MUL2;
    float res[DI];
    load_res<MUL_IN, UV, DI, X_OFF>(wrow + W_OFF + lid * 8, xsh, res);
    if (B_OFF >= 0) res[0] += bsh[B_OFF + lid];
    constexpr float inv = 1.0f / (float)MUL_IN;
    #pragma unroll
    for (int ab = 0; ab < D1 * D2; ab++) {
        int a = ab / D2, b = ab % D2;
        float acc = 0.0f;
        #pragma unroll
        for (int k = 0; k < DI; k++)
            acc += w3s[W3J_OFF + ab * DI + k] * res[k];
        osh[(ROW_OFF + u * D1 + a) * OUTD + COL_OFF + v * D2 + b] = acc * inv;
    }
}

template<int MUL_IN, int MUL1, int MUL2, int D1, int D2, int DI,
         int W_OFF, int W3J_OFF, int ROW_OFF, int COL_OFF, int X_OFF, int NSPLIT>
__device__ __forceinline__ void path_split(int uv, int split, const __half* __restrict__ wrow,
                                           const float* xsh, const float* w3s, float* osh) {
    constexpr int UV = MUL1 * MUL2;
    int u = uv / MUL2, v = uv % MUL2;
    float res[DI];
    load_res<MUL_IN, UV, DI, X_OFF>(wrow + W_OFF + uv * 8, xsh, res);
    constexpr float inv = 1.0f / (float)MUL_IN;
    #pragma unroll
    for (int ab = split; ab < D1 * D2; ab += NSPLIT) {
        int a = ab / D2, b = ab % D2;
        float acc = 0.0f;
        #pragma unroll
        for (int k = 0; k < DI; k++)
            acc += w3s[W3J_OFF + ab * DI + k] * res[k];
        osh[(ROW_OFF + u * D1 + a) * OUTD + COL_OFF + v * D2 + b] = acc * inv;
    }
}

template<int MI_A, int DI_A, int W_A, int B_A, int W3_A, int XO_A,
         int MI_B, int DI_B, int W_B, int W3_B, int XO_B,
         int MUL1, int MUL2, int D1, int D2, int ROW_OFF, int COL_OFF, int NSPLIT>
__device__ __forceinline__ void path_pair(int uv, int split, const __half* __restrict__ wrow,
                                          const float* xsh, const float* bsh,
                                          const float* w3s, float* osh) {
    constexpr int UV = MUL1 * MUL2;
    int u = uv / MUL2, v = uv % MUL2;
    float ra[DI_A], rb[DI_B];
    load_res<MI_A, UV, DI_A, XO_A>(wrow + W_A + uv * 8, xsh, ra);
    if (B_A >= 0) ra[0] += bsh[B_A + uv];
    load_res<MI_B, UV, DI_B, XO_B>(wrow + W_B + uv * 8, xsh, rb);
    constexpr float invA = 1.0f / (float)MI_A;
    constexpr float invB = 1.0f / (float)MI_B;
    #pragma unroll
    for (int ab = split; ab < D1 * D2; ab += NSPLIT) {
        int a = ab / D2, b = ab % D2;
        float aA = 0.0f;
        #pragma unroll
        for (int k = 0; k < DI_A; k++) aA += w3s[W3_A + ab * DI_A + k] * ra[k];
        float aB = 0.0f;
        #pragma unroll
        for (int k = 0; k < DI_B; k++) aB += w3s[W3_B + ab * DI_B + k] * rb[k];
        osh[(ROW_OFF + u * D1 + a) * OUTD + COL_OFF + v * D2 + b] = aA * invA + aB * invB;
    }
}

#define ETHREADS 512
__global__ __launch_bounds__(ETHREADS) void expand_kernel(
    const float* __restrict__ x_in, float* __restrict__ out) {
    __shared__ float xsh[D_IN];
    __shared__ float bsh[NB];
    __shared__ float w3s[363];
    __shared__ __align__(16) float osh[OUTD * OUTD];
    int n = blockIdx.x, tid = threadIdx.x;
    const __half* wrow = g_weight_h + (size_t)n * NPW;

    for (int i = tid; i < D_IN; i += ETHREADS) xsh[i] = x_in[n * D_IN + i];
    for (int i = tid; i < NB; i += ETHREADS) bsh[i] = g_bias[n * NB + i];
    for (int i = tid; i < 363; i += ETHREADS) w3s[i] = g_w3j[i];
    __syncthreads();

    // Wave 1: large paths
    if (tid < 256) {
        path_fn<32, 16, 16, 1, 1, 1,     0,   0,   0,   0,  0,  0>(tid,       wrow, xsh, bsh, w3s, osh);
    } else if (tid < 384) {
        path_fn<16, 16,  8, 1, 3, 3, 10752,  -1,  35,   0, 16, 32>(tid - 256, wrow, xsh, bsh, w3s, osh);
    } else {
        path_fn<16,  8, 16, 3, 1, 3, 12800,  -1,  44,  16,  0, 32>(tid - 384, wrow, xsh, bsh, w3s, osh);
    }

    // Wave 2: remaining blocks, warp-uniform, balanced
    if (tid < 128) {
        path_pair<32, 1,  8192, 256,   1,  0,
                   8, 5, 16384,      168, 80,
                   8, 8, 3, 3, 16, 16, 2>(tid >> 1, tid & 1, wrow, xsh, bsh, w3s, osh);
    } else if (tid < 192) {
        int t = tid - 128;
        path_pair<32, 1, 10240, 320,  10,  0,
                   8, 5, 17408,      238, 80,
                   4, 4, 5, 5, 40, 40, 4>(t >> 2, t & 3, wrow, xsh, bsh, w3s, osh);
    } else if (tid < 256) {
        path_fn< 8, 16,  4, 1, 5, 5, 15872,  -1, 143,   0, 40, 80>(tid - 192, wrow, xsh, bsh, w3s, osh);
    } else if (tid < 320) {
        path_fn< 8,  4, 16, 5, 1, 5, 16896,  -1, 213,  40,  0, 80>(tid - 256, wrow, xsh, bsh, w3s, osh);
    } else if (tid < 384) {
        int t = tid - 320;
        path_split<16,  8,  4, 3, 5, 3, 14848,  53, 16, 40, 32, 2>(t >> 1, t & 1, wrow, xsh, w3s, osh);
    } else if (tid < 448) {
        int t = tid - 384;
        path_split<16,  4,  8, 5, 3, 3, 15360,  98, 40, 16, 32, 2>(t >> 1, t & 1, wrow, xsh, w3s, osh);
    }
    __syncthreads();

    const float4* osh4 = (const float4*)osh;
    float4* out4 = (float4*)(out + (size_t)n * (OUTD * OUTD));
    for (int i = tid; i < OUTD * OUTD / 4; i += ETHREADS)
        out4[i] = osh4[i];
}

// ---------------- launch ----------------
extern "C" void kernel_launch(void* const* d_in, const int* in_sizes, int n_in,
                              void* d_out, int out_size) {
    const float* x_in  = (const float*)d_in[0];
    const float* embed = (const float*)d_in[1];
    const float* w1w   = (const float*)d_in[2];
    const float* b1w   = (const float*)d_in[3];
    const float* w2w   = (const float*)d_in[4];
    const float* b2w   = (const float*)d_in[5];
    const float* w1b   = (const float*)d_in[6];
    const float* b1b   = (const float*)d_in[7];
    const float* w2b   = (const float*)d_in[8];
    const float* b2b   = (const float*)d_in[9];
    float* out = (float*)d_out;

    cudaFuncSetAttribute(gemm_mma_kernel, cudaFuncAttributeMaxDynamicSharedMemorySize, GH_TOT);

    w3j_init_kernel<<<1, 384>>>();
    permute_kernel<<<(NPW + 255) / 256, 256>>>(w2w, b2w);
    transpose_w2b_kernel<<<NB, 64>>>(w2b);
    hidden_kernel<<<NN / HNODES, 128>>>(embed, w1w, b1w, w1b, b1b);
    bias_kernel<<<NN / BNODES, 352>>>(b2b);
    gemm_mma_kernel<<<dim3(NPW / 128, NN / 128), 256, GH_TOT>>>();
    expand_kernel<<<NN, ETHREADS>>>(x_in, out);
}